// round 1
// baseline (speedup 1.0000x reference)
#include <cuda_runtime.h>

// Shapes (fixed by the problem)
#define BB 2
#define LL 4096
#define DIN 512
#define HH 8
#define DK 64
#define DV 64
#define DOUT 512

// ---------------------------------------------------------------------------
// Scratch (no allocations allowed -> __device__ globals)
// ---------------------------------------------------------------------------
__device__ float g_Gpart[4 * BB * DIN * DIN];   // split-K partials for Gram (8 MB)
__device__ float g_G [BB * DIN * DIN];          // G[b]  = x^T x            (2 MB)
__device__ float g_P [BB * HH * DK * DIN];      // P[b,h] = Wk^T G          (2 MB)
__device__ float g_M2[BB * HH * DK * DV];       // M[b,h] = P Wv            (256 KB)
__device__ float g_T2[BB * DIN * (HH * DV)];    // T2cat[b] (512 x 512)     (2 MB)
__device__ float g_F [BB * DIN * DOUT];         // F[b] (512 x 512)         (2 MB)

// ---------------------------------------------------------------------------
// Generic tiled fp32 GEMM: C[b,h] (+)= op(A[b,h]) * B[b,h]
//   TRANSA=0: A is (M x K) row-major, lda = row stride
//   TRANSA=1: A is (K x M) row-major, lda = row stride  (i.e. computes A^T * B)
//   B always (K x N) row-major. C (M x N) row-major.
//   Batch: grid.z = batches * nh * nsplit;  z -> (b, h, split)
//   Split-K: each split writes its own partial buffer slice (deterministic).
// Tile: 64x64, 256 threads, 4x4 per thread, KT=16.
// ---------------------------------------------------------------------------
template <int TRANSA>
__global__ __launch_bounds__(256) void gemm64(
    const float* __restrict__ A, const float* __restrict__ B, float* __restrict__ C,
    int M, int N, int K,
    int lda, int ldb, int ldc,
    long sAb, long sAh, long sBb, long sBh, long sCb, long sCh,
    int nh, int nsplit, long splitStride)
{
    int z = blockIdx.z;
    int split = z % nsplit; z /= nsplit;
    int h = z % nh;
    int b = z / nh;
    A += (long)b * sAb + (long)h * sAh;
    B += (long)b * sBb + (long)h * sBh;
    C += (long)b * sCb + (long)h * sCh + (long)split * splitStride;

    const int Kc = K / nsplit;
    const int k0 = split * Kc;

    __shared__ float As[16][64];
    __shared__ float Bs[16][64];

    const int m0 = blockIdx.y * 64;
    const int n0 = blockIdx.x * 64;
    const int tid = threadIdx.x;
    const int tx = tid & 15;       // 0..15 -> output cols tx*4..tx*4+3
    const int ty = tid >> 4;       // 0..15 -> output rows ty*4..ty*4+3

    float acc[4][4];
#pragma unroll
    for (int i = 0; i < 4; i++)
#pragma unroll
        for (int j = 0; j < 4; j++) acc[i][j] = 0.f;

    for (int kt = 0; kt < Kc; kt += 16) {
        // ---- load A tile into As[k][m] ----
        if (TRANSA) {
            int k  = tid >> 4;            // 16 rows
            int m4 = (tid & 15) * 4;      // 64 cols / 4
            float4 v = *reinterpret_cast<const float4*>(
                &A[(long)(k0 + kt + k) * lda + m0 + m4]);
            *reinterpret_cast<float4*>(&As[k][m4]) = v;
        } else {
            int m  = tid >> 2;            // 64 rows
            int k4 = (tid & 3) * 4;       // 16 cols / 4
            float4 v = *reinterpret_cast<const float4*>(
                &A[(long)(m0 + m) * lda + (k0 + kt + k4)]);
            As[k4 + 0][m] = v.x;
            As[k4 + 1][m] = v.y;
            As[k4 + 2][m] = v.z;
            As[k4 + 3][m] = v.w;
        }
        // ---- load B tile into Bs[k][n] ----
        {
            int k  = tid >> 4;
            int n4 = (tid & 15) * 4;
            float4 v = *reinterpret_cast<const float4*>(
                &B[(long)(k0 + kt + k) * ldb + n0 + n4]);
            *reinterpret_cast<float4*>(&Bs[k][n4]) = v;
        }
        __syncthreads();

#pragma unroll
        for (int k = 0; k < 16; k++) {
            float4 a = *reinterpret_cast<const float4*>(&As[k][ty * 4]);
            float4 bb = *reinterpret_cast<const float4*>(&Bs[k][tx * 4]);
            float av[4] = {a.x, a.y, a.z, a.w};
            float bv[4] = {bb.x, bb.y, bb.z, bb.w};
#pragma unroll
            for (int i = 0; i < 4; i++)
#pragma unroll
                for (int j = 0; j < 4; j++)
                    acc[i][j] += av[i] * bv[j];
        }
        __syncthreads();
    }

    // ---- store ----
#pragma unroll
    for (int i = 0; i < 4; i++) {
        int m = m0 + ty * 4 + i;
        float4 v = make_float4(acc[i][0], acc[i][1], acc[i][2], acc[i][3]);
        *reinterpret_cast<float4*>(&C[(long)m * ldc + n0 + tx * 4]) = v;
    }
}

// Deterministic fixed-order reduction of the 4 split-K partials
__global__ void reduce4(float* __restrict__ dst, const float* __restrict__ src, int n)
{
    int i = blockIdx.x * 256 + threadIdx.x;
    if (i < n)
        dst[i] = ((src[i] + src[n + i]) + src[2 * n + i]) + src[3 * n + i];
}

// ---------------------------------------------------------------------------
extern "C" void kernel_launch(void* const* d_in, const int* in_sizes, int n_in,
                              void* d_out, int out_size)
{
    const float* x  = (const float*)d_in[0];
    const float* Wq = (const float*)d_in[1];
    const float* Wk = (const float*)d_in[2];
    const float* Wv = (const float*)d_in[3];
    const float* Wo = (const float*)d_in[4];
    float* out = (float*)d_out;

    float *G, *Gp, *P, *M2, *T2, *F;
    cudaGetSymbolAddress((void**)&G,  g_G);
    cudaGetSymbolAddress((void**)&Gp, g_Gpart);
    cudaGetSymbolAddress((void**)&P,  g_P);
    cudaGetSymbolAddress((void**)&M2, g_M2);
    cudaGetSymbolAddress((void**)&T2, g_T2);
    cudaGetSymbolAddress((void**)&F,  g_F);

    const long LD   = (long)LL * DIN;      // x batch stride
    const long GS   = (long)DIN * DIN;     // 512*512
    const long WKS  = (long)DIN * DK;      // per-head Wk/Wq/Wv stride
    const long PSH  = (long)DK * DIN;      // per-head P stride
    const long PSB  = (long)HH * PSH;
    const long MSH  = (long)DK * DV;
    const long MSB  = (long)HH * MSH;

    // 1) G[b] = x[b]^T x[b]   (split-K=4, deterministic partials)
    gemm64<1><<<dim3(8, 8, BB * 4), 256>>>(
        x, x, Gp, DIN, DIN, LL,
        DIN, DIN, DIN,
        LD, 0, LD, 0, GS, 0,
        /*nh=*/1, /*nsplit=*/4, /*splitStride=*/(long)BB * GS);
    reduce4<<<(BB * DIN * DIN + 255) / 256, 256>>>(G, Gp, BB * DIN * DIN);

    // 2) P[b,h] = Wk[h]^T @ G[b]      (64 x 512, K=512)
    gemm64<1><<<dim3(8, 1, BB * HH), 256>>>(
        Wk, G, P, DK, DIN, DIN,
        DK, DIN, DIN,
        0, WKS, GS, 0, PSB, PSH,
        /*nh=*/HH, 1, 0);

    // 3) M[b,h] = P[b,h] @ Wv[h]      (64 x 64, K=512)
    gemm64<0><<<dim3(1, 1, BB * HH), 256>>>(
        P, Wv, M2, DK, DV, DIN,
        DIN, DV, DV,
        PSB, PSH, 0, WKS, MSB, MSH,
        HH, 1, 0);

    // 4) T2cat[b][:, h*64:(h+1)*64] = Wq[h] @ M[b,h]   (512 x 64, K=64)
    gemm64<0><<<dim3(1, 8, BB * HH), 256>>>(
        Wq, M2, T2, DIN, DV, DK,
        DK, DV, HH * DV,
        0, WKS, MSB, MSH, (long)DIN * HH * DV, (long)DV,
        HH, 1, 0);

    // 5) F[b] = T2cat[b] @ Wo_flat    (512 x 512, K=512); Wo (8,64,512) is already (512,512) row-major
    gemm64<0><<<dim3(8, 8, BB), 256>>>(
        T2, Wo, F, DIN, DOUT, HH * DV,
        HH * DV, DOUT, DOUT,
        (long)DIN * HH * DV, 0, 0, 0, (long)DIN * DOUT, 0,
        1, 1, 0);

    // 6) out[b] = x[b] @ F[b]         (4096 x 512, K=512)
    gemm64<0><<<dim3(8, 64, BB), 256>>>(
        x, F, out, LL, DOUT, DIN,
        DIN, DOUT, DOUT,
        LD, 0, (long)DIN * DOUT, 0, (long)LL * DOUT, 0,
        1, 1, 0);
}

// round 3
// speedup vs baseline: 1.0848x; 1.0848x over previous
#include <cuda_runtime.h>

#define BB 2
#define LL 4096
#define DIN 512
#define HH 8
#define DK 64
#define DV 64
#define DOUT 512

// ---------------------------------------------------------------------------
// Scratch (__device__ globals; no allocations allowed)
// ---------------------------------------------------------------------------
__device__ float g_Gpart[8 * BB * DIN * DIN];     // Gram split-K partials (16 MB)
__device__ float g_G [BB * DIN * DIN];            // G[b]  = x^T x
__device__ float g_P [BB * HH * DK * DIN];        // P[b,h] = Wk^T G
__device__ float g_Mpart[8 * BB * HH * DK * DV];  // step-3 split-K partials
__device__ float g_M2[BB * HH * DK * DV];         // M[b,h] = P Wv
__device__ float g_T2[BB * DIN * (HH * DV)];      // T2cat[b] (512 x 512)
__device__ float g_F [BB * DIN * DOUT];           // F[b] (512 x 512)

// ---------------------------------------------------------------------------
// f32x2 packed helpers (Blackwell packed fp32: 2 FMA per instruction)
// ---------------------------------------------------------------------------
__device__ __forceinline__ unsigned long long pk2(float a) {
    unsigned long long r;
    asm("mov.b64 %0, {%1, %1};" : "=l"(r) : "f"(a));
    return r;
}
__device__ __forceinline__ void fma2(unsigned long long& d,
                                     unsigned long long a, unsigned long long b) {
    asm("fma.rn.f32x2 %0, %1, %2, %0;" : "+l"(d) : "l"(a), "l"(b));
}

// ---------------------------------------------------------------------------
// Big GEMM: 128x128 tile, 256 threads, 8x8 per thread, KT=8, double-buffered.
//   TRANSA=1: computes A^T * B  (A is K x M row-major)
//   TRANSA=0: computes A   * B  (A is M x K row-major)
//   B (K x N) row-major, C (M x N) row-major.
//   grid.z = batches * nsplit (split-K with separate deterministic partials)
// Requires: M%128==0, N%128==0, (K/nsplit)%8==0.
// ---------------------------------------------------------------------------
template <int TRANSA>
__global__ __launch_bounds__(256) void gemm128(
    const float* __restrict__ A, const float* __restrict__ B, float* __restrict__ C,
    int K, int lda, int ldb, int ldc,
    long sAb, long sBb, long sCb,
    int nsplit, long splitStride)
{
    int z = blockIdx.z;
    const int split = z % nsplit;
    const int b = z / nsplit;
    A += (long)b * sAb;
    B += (long)b * sBb;
    C += (long)b * sCb + (long)split * splitStride;

    const int Kc = K / nsplit;
    const int k0 = split * Kc;
    const int ntiles = Kc / 8;

    __shared__ float As[2][8][128];
    __shared__ float Bs[2][8][128];

    const int m0 = blockIdx.y * 128;
    const int n0 = blockIdx.x * 128;
    const int tid = threadIdx.x;
    const int tx = tid & 15;       // output col group: tx*8 .. tx*8+7
    const int ty = tid >> 4;       // output row group: ty*8 .. ty*8+7

    // global load indexing
    const int kb = tid >> 5, nb4 = (tid & 31) * 4;           // B tile
    const int ka_t = tid >> 5, ma4 = (tid & 31) * 4;         // A tile (TRANSA=1)
    const int ma_n = tid >> 1, ka4 = (tid & 1) * 4;          // A tile (TRANSA=0)

    unsigned long long acc[8][4];
#pragma unroll
    for (int i = 0; i < 8; i++)
#pragma unroll
        for (int j = 0; j < 4; j++) acc[i][j] = 0ull;

    // ---- preload tile 0 ----
    float4 ra, rb;
    {
        const int kt = k0;
        if (TRANSA)
            ra = *reinterpret_cast<const float4*>(&A[(long)(kt + ka_t) * lda + m0 + ma4]);
        else
            ra = *reinterpret_cast<const float4*>(&A[(long)(m0 + ma_n) * lda + kt + ka4]);
        rb = *reinterpret_cast<const float4*>(&B[(long)(kt + kb) * ldb + n0 + nb4]);
    }
    if (TRANSA) {
        *reinterpret_cast<float4*>(&As[0][ka_t][ma4]) = ra;
    } else {
        As[0][ka4 + 0][ma_n] = ra.x;
        As[0][ka4 + 1][ma_n] = ra.y;
        As[0][ka4 + 2][ma_n] = ra.z;
        As[0][ka4 + 3][ma_n] = ra.w;
    }
    *reinterpret_cast<float4*>(&Bs[0][kb][nb4]) = rb;
    __syncthreads();

    for (int t = 0; t < ntiles; t++) {
        const int cur = t & 1;
        const int nxt = cur ^ 1;

        // prefetch next tile (global -> regs)
        if (t + 1 < ntiles) {
            const int kt = k0 + (t + 1) * 8;
            if (TRANSA)
                ra = *reinterpret_cast<const float4*>(&A[(long)(kt + ka_t) * lda + m0 + ma4]);
            else
                ra = *reinterpret_cast<const float4*>(&A[(long)(m0 + ma_n) * lda + kt + ka4]);
            rb = *reinterpret_cast<const float4*>(&B[(long)(kt + kb) * ldb + n0 + nb4]);
        }

        // compute on current buffer
#pragma unroll
        for (int k = 0; k < 8; k++) {
            float4 a0 = *reinterpret_cast<const float4*>(&As[cur][k][ty * 8]);
            float4 a1 = *reinterpret_cast<const float4*>(&As[cur][k][ty * 8 + 4]);
            ulonglong2 b0 = *reinterpret_cast<const ulonglong2*>(&Bs[cur][k][tx * 8]);
            ulonglong2 b1 = *reinterpret_cast<const ulonglong2*>(&Bs[cur][k][tx * 8 + 4]);
            unsigned long long bv[4] = {b0.x, b0.y, b1.x, b1.y};
            float av[8] = {a0.x, a0.y, a0.z, a0.w, a1.x, a1.y, a1.z, a1.w};
#pragma unroll
            for (int i = 0; i < 8; i++) {
                unsigned long long ap = pk2(av[i]);
#pragma unroll
                for (int j = 0; j < 4; j++) fma2(acc[i][j], ap, bv[j]);
            }
        }

        // stage next tile regs -> other smem buffer
        if (t + 1 < ntiles) {
            if (TRANSA) {
                *reinterpret_cast<float4*>(&As[nxt][ka_t][ma4]) = ra;
            } else {
                As[nxt][ka4 + 0][ma_n] = ra.x;
                As[nxt][ka4 + 1][ma_n] = ra.y;
                As[nxt][ka4 + 2][ma_n] = ra.z;
                As[nxt][ka4 + 3][ma_n] = ra.w;
            }
            *reinterpret_cast<float4*>(&Bs[nxt][kb][nb4]) = rb;
            __syncthreads();
        }
    }

    // ---- store C ----
#pragma unroll
    for (int i = 0; i < 8; i++) {
        const int m = m0 + ty * 8 + i;
        const float* f = reinterpret_cast<const float*>(acc[i]);
        float4 v0 = make_float4(f[0], f[1], f[2], f[3]);
        float4 v1 = make_float4(f[4], f[5], f[6], f[7]);
        *reinterpret_cast<float4*>(&C[(long)m * ldc + n0 + tx * 8]) = v0;
        *reinterpret_cast<float4*>(&C[(long)m * ldc + n0 + tx * 8 + 4]) = v1;
    }
}

// ---------------------------------------------------------------------------
// Small/medium GEMM: 64x64 tile, 256 threads, 4x4 per thread, KT=16.
// ---------------------------------------------------------------------------
template <int TRANSA>
__global__ __launch_bounds__(256) void gemm64(
    const float* __restrict__ A, const float* __restrict__ B, float* __restrict__ C,
    int M, int N, int K,
    int lda, int ldb, int ldc,
    long sAb, long sAh, long sBb, long sBh, long sCb, long sCh,
    int nh, int nsplit, long splitStride)
{
    int z = blockIdx.z;
    int split = z % nsplit; z /= nsplit;
    int h = z % nh;
    int b = z / nh;
    A += (long)b * sAb + (long)h * sAh;
    B += (long)b * sBb + (long)h * sBh;
    C += (long)b * sCb + (long)h * sCh + (long)split * splitStride;

    const int Kc = K / nsplit;
    const int k0 = split * Kc;

    __shared__ float As[16][64];
    __shared__ float Bs[16][64];

    const int m0 = blockIdx.y * 64;
    const int n0 = blockIdx.x * 64;
    const int tid = threadIdx.x;
    const int tx = tid & 15;
    const int ty = tid >> 4;

    float acc[4][4];
#pragma unroll
    for (int i = 0; i < 4; i++)
#pragma unroll
        for (int j = 0; j < 4; j++) acc[i][j] = 0.f;

    for (int kt = 0; kt < Kc; kt += 16) {
        if (TRANSA) {
            int k  = tid >> 4;
            int m4 = (tid & 15) * 4;
            float4 v = *reinterpret_cast<const float4*>(
                &A[(long)(k0 + kt + k) * lda + m0 + m4]);
            *reinterpret_cast<float4*>(&As[k][m4]) = v;
        } else {
            int m  = tid >> 2;
            int k4 = (tid & 3) * 4;
            float4 v = *reinterpret_cast<const float4*>(
                &A[(long)(m0 + m) * lda + (k0 + kt + k4)]);
            As[k4 + 0][m] = v.x;
            As[k4 + 1][m] = v.y;
            As[k4 + 2][m] = v.z;
            As[k4 + 3][m] = v.w;
        }
        {
            int k  = tid >> 4;
            int n4 = (tid & 15) * 4;
            float4 v = *reinterpret_cast<const float4*>(
                &B[(long)(k0 + kt + k) * ldb + n0 + n4]);
            *reinterpret_cast<float4*>(&Bs[k][n4]) = v;
        }
        __syncthreads();

#pragma unroll
        for (int k = 0; k < 16; k++) {
            float4 a = *reinterpret_cast<const float4*>(&As[k][ty * 4]);
            float4 bb = *reinterpret_cast<const float4*>(&Bs[k][tx * 4]);
            float av[4] = {a.x, a.y, a.z, a.w};
            float bv[4] = {bb.x, bb.y, bb.z, bb.w};
#pragma unroll
            for (int i = 0; i < 4; i++)
#pragma unroll
                for (int j = 0; j < 4; j++)
                    acc[i][j] += av[i] * bv[j];
        }
        __syncthreads();
    }

#pragma unroll
    for (int i = 0; i < 4; i++) {
        int m = m0 + ty * 4 + i;
        float4 v = make_float4(acc[i][0], acc[i][1], acc[i][2], acc[i][3]);
        *reinterpret_cast<float4*>(&C[(long)m * ldc + n0 + tx * 4]) = v;
    }
}

// Deterministic fixed-order reduction of split-K partials
template <int P>
__global__ void reduceP(float* __restrict__ dst, const float* __restrict__ src, int n)
{
    int i = blockIdx.x * 256 + threadIdx.x;
    if (i < n) {
        float s = 0.f;
#pragma unroll
        for (int p = 0; p < P; p++) s += src[(long)p * n + i];
        dst[i] = s;
    }
}

// ---------------------------------------------------------------------------
extern "C" void kernel_launch(void* const* d_in, const int* in_sizes, int n_in,
                              void* d_out, int out_size)
{
    const float* x  = (const float*)d_in[0];
    const float* Wq = (const float*)d_in[1];
    const float* Wk = (const float*)d_in[2];
    const float* Wv = (const float*)d_in[3];
    const float* Wo = (const float*)d_in[4];
    float* out = (float*)d_out;

    float *G, *Gp, *P, *Mp, *M2, *T2, *F;
    cudaGetSymbolAddress((void**)&G,  g_G);
    cudaGetSymbolAddress((void**)&Gp, g_Gpart);
    cudaGetSymbolAddress((void**)&P,  g_P);
    cudaGetSymbolAddress((void**)&Mp, g_Mpart);
    cudaGetSymbolAddress((void**)&M2, g_M2);
    cudaGetSymbolAddress((void**)&T2, g_T2);
    cudaGetSymbolAddress((void**)&F,  g_F);

    const long LD   = (long)LL * DIN;      // x batch stride
    const long GS   = (long)DIN * DIN;     // 512*512
    const long WKS  = (long)DIN * DK;      // per-head W stride
    const long PSH  = (long)DK * DIN;
    const long PSB  = (long)HH * PSH;
    const long MSH  = (long)DK * DV;
    const long MSB  = (long)HH * MSH;

    // 1) G[b] = x[b]^T x[b]   128-tile, split-K=8 -> 256 CTAs
    gemm128<1><<<dim3(4, 4, BB * 8), 256>>>(
        x, x, Gp, LL, DIN, DIN, DIN,
        LD, LD, GS, /*nsplit=*/8, /*splitStride=*/(long)BB * GS);
    reduceP<8><<<(BB * DIN * DIN + 255) / 256, 256>>>(G, Gp, BB * DIN * DIN);

    // 2) P[b,h] = Wk[h]^T @ G[b]      (64 x 512, K=512), 128 CTAs
    gemm64<1><<<dim3(8, 1, BB * HH), 256>>>(
        Wk, G, P, DK, DIN, DIN,
        DK, DIN, DIN,
        0, WKS, GS, 0, PSB, PSH,
        HH, 1, 0);

    // 3) M[b,h] = P[b,h] @ Wv[h]      (64 x 64, K=512), split-K=8 -> 128 CTAs
    gemm64<0><<<dim3(1, 1, BB * HH * 8), 256>>>(
        P, Wv, Mp, DK, DV, DIN,
        DIN, DV, DV,
        PSB, PSH, 0, WKS, MSB, MSH,
        HH, /*nsplit=*/8, /*splitStride=*/(long)BB * HH * DK * DV);
    reduceP<8><<<(BB * HH * DK * DV + 255) / 256, 256>>>(M2, Mp, BB * HH * DK * DV);

    // 4) T2cat[b][:, h*64:(h+1)*64] = Wq[h] @ M[b,h]   (512 x 64, K=64), 128 CTAs
    gemm64<0><<<dim3(1, 8, BB * HH), 256>>>(
        Wq, M2, T2, DIN, DV, DK,
        DK, DV, HH * DV,
        0, WKS, MSB, MSH, (long)DIN * HH * DV, (long)DV,
        HH, 1, 0);

    // 5) F[b] = T2cat[b] @ Wo_flat    (512 x 512, K=512), 128 CTAs
    gemm64<0><<<dim3(8, 8, BB), 256>>>(
        T2, Wo, F, DIN, DOUT, HH * DV,
        HH * DV, DOUT, DOUT,
        (long)DIN * HH * DV, 0, 0, 0, (long)DIN * DOUT, 0,
        1, 1, 0);

    // 6) out[b] = x[b] @ F[b]         (4096 x 512, K=512), 128-tile, 256 CTAs
    //    BUGFIX vs round 2: F batch stride was 0 (both batches read F[0]).
    gemm128<0><<<dim3(4, 32, BB), 256>>>(
        x, F, out, DIN, DIN, DOUT, DOUT,
        LD, (long)DIN * DOUT, (long)LL * DOUT, 1, 0);
}